// round 11
// baseline (speedup 1.0000x reference)
#include <cuda_runtime.h>
#include <cstdint>

// Fixed problem shapes
static constexpr int NP     = 128;           // partitions
static constexpr int Cc     = 32;            // key channels
static constexpr int Dd     = 128;           // value/query dim
static constexpr int Bb     = 4;
static constexpr int Ss     = 2048;
static constexpr int Kk     = 2;
static constexpr int NPAIRS = Bb * Ss * Kk;  // 16384
static constexpr int NTOK   = Bb * Ss;       // 8192

static constexpr int NTHR   = 1024;
static constexpr int NBLK   = 2 * NP;        // 256 blocks = (partition, half)
static constexpr int HALFN  = NPAIRS / 2;    // 8192 pairs per half
static constexpr int PER    = HALFN / 4 / NTHR;    // 2 int4 per thread
static constexpr int CAP    = 512;           // per-(p,half) capacity (mean 64, sigma 8)

// Persistent device state (g_P fully rewritten each launch; flags/epochs are
// monotonic counters -> correct across graph replays without resets).
__device__ float             g_P[2 * NP * Dd];   // per-(half,partition) rows
__device__ volatile unsigned g_flag[NBLK];       // row-published epochs (0-init)
__device__ unsigned          g_epoch[NBLK];      // per-block launch counters

// ---------------------------------------------------------------------------
// 256 blocks x 1024 threads, 2 CTAs/SM (regs capped by launch_bounds -> all
// co-resident; every block produces its row before consuming -> no deadlock).
// Block (p,h):
//   Phase 1:   scan half h of idx (2 int4/thread), two-level shfl scan ->
//              deterministic compaction of ~64 matching pair indices.
//   Phase 1.5: w[m] = mean_c keys[j_m,:], 8 threads/row octet-shfl.
//   Phase 2:   float4 gather thread=(slice,d4); transpose + warp-shfl
//              reduce -> g_P[h][p] row; threadfence; flag[p*2+h]=epoch.
//   Phase 3:   per-warp dataflow wait on the 4 flags its token needs, then
//              out = (P0[i0]+P1[i0]+P0[i1]+P1[i1]) * q, 1 float4/thread.
// ---------------------------------------------------------------------------
__global__ void __launch_bounds__(NTHR, 2) k_fused(
    const int*   __restrict__ idx,
    const float* __restrict__ keys,
    const float* __restrict__ values,
    const float* __restrict__ q,
    float*       __restrict__ out)
{
    __shared__ int      js[CAP];
    __shared__ float    wls[CAP];
    __shared__ int      wsum[32];
    __shared__ float4   red4[32][33];        // padded transpose buffer
    __shared__ unsigned s_epoch;

    const int p    = blockIdx.x >> 1;
    const int h    = blockIdx.x & 1;
    const int tid  = threadIdx.x;
    const int lane = tid & 31;
    const int wid  = tid >> 5;
    const int base = blockIdx.x * NTHR + tid;  // phase-3 float4 index

    // Per-block launch epoch: every block bumps its own counter once per
    // launch, so all blocks compute the same value. Monotonic, replay-safe.
    if (tid == 0) s_epoch = atomicAdd(&g_epoch[blockIdx.x], 1u) + 1u;

    // ---- Phase 1a: strided-coalesced idx load (2 int4/thread), count
    const int4* idx4 = (const int4*)idx + h * (HALFN / 4);
    int4 my[PER];
    int cnt = 0;
    #pragma unroll
    for (int i = 0; i < PER; i++) {
        my[i] = idx4[i * NTHR + tid];
        cnt += (my[i].x == p) + (my[i].y == p) + (my[i].z == p) + (my[i].w == p);
    }

    // ---- Phase 1b: two-level exclusive scan (warp shfl + 32-entry top)
    int inc = cnt;
    #pragma unroll
    for (int o = 1; o < 32; o <<= 1) {
        int v = __shfl_up_sync(0xFFFFFFFFu, inc, o);
        if (lane >= o) inc += v;
    }
    if (lane == 31) wsum[wid] = inc;
    __syncthreads();
    if (wid == 0) {
        int v = wsum[lane];
        #pragma unroll
        for (int o = 1; o < 32; o <<= 1) {
            int u = __shfl_up_sync(0xFFFFFFFFu, v, o);
            if (lane >= o) v += u;
        }
        wsum[lane] = v;                        // inclusive prefix of warp totals
    }
    __syncthreads();
    int n   = wsum[31];
    int pos = (wid ? wsum[wid - 1] : 0) + (inc - cnt);

    // ---- Phase 1c: emit matched pair indices (fixed deterministic order)
    #pragma unroll
    for (int i = 0; i < PER; i++) {
        const int j = h * HALFN + (i * NTHR + tid) * 4;
        if (my[i].x == p && pos < CAP) js[pos++] = j + 0;
        if (my[i].y == p && pos < CAP) js[pos++] = j + 1;
        if (my[i].z == p && pos < CAP) js[pos++] = j + 2;
        if (my[i].w == p && pos < CAP) js[pos++] = j + 3;
    }
    if (n > CAP) n = CAP;
    __syncthreads();

    // ---- Phase 1.5: weights, 8 threads per 128B key row, octet shfl.
    {
        const int lane8 = tid & 7;
        const int row8  = tid >> 3;
        for (int b = 0; b < n; b += NTHR / 8) {
            const int m = b + row8;
            float s = 0.f;
            if (m < n) {
                float4 v = ((const float4*)keys)[(size_t)js[m] * (Cc / 4) + lane8];
                s = (v.x + v.y) + (v.z + v.w);
            }
            s += __shfl_xor_sync(0xFFFFFFFFu, s, 1);
            s += __shfl_xor_sync(0xFFFFFFFFu, s, 2);
            s += __shfl_xor_sync(0xFFFFFFFFu, s, 4);
            if (m < n && lane8 == 0) wls[m] = s * (1.0f / Cc);
        }
    }
    __syncthreads();

    // ---- Phase 2: float4 gather, thread=(slice,d4); ~2 matches/thread.
    {
        const int slice = tid >> 5;
        const int d4    = tid & 31;
        const float4* V4 = (const float4*)values;
        float4 acc = make_float4(0.f, 0.f, 0.f, 0.f);
        for (int m = slice; m < n; m += 32) {
            const float w = wls[m];
            float4 v = V4[(js[m] >> 1) * 32 + d4];
            acc.x += w * v.x; acc.y += w * v.y;
            acc.z += w * v.z; acc.w += w * v.w;
        }
        red4[slice][d4] = acc;
        __syncthreads();
        // warp-transpose reduce: warp `wid` owns column d4=wid, lanes=slices
        float4 v = red4[lane][wid];
        #pragma unroll
        for (int o = 16; o >= 1; o >>= 1) {
            v.x += __shfl_down_sync(0xFFFFFFFFu, v.x, o);
            v.y += __shfl_down_sync(0xFFFFFFFFu, v.y, o);
            v.z += __shfl_down_sync(0xFFFFFFFFu, v.z, o);
            v.w += __shfl_down_sync(0xFFFFFFFFu, v.w, o);
        }
        if (lane == 0)
            ((float4*)g_P)[(h * NP + p) * 32 + wid] = v;
    }

    // ---- Publish: this block's row is done -> set its flag to the epoch.
    __syncthreads();
    const unsigned ep = s_epoch;
    if (tid == 0) {
        __threadfence();                       // drain row stores to L2
        g_flag[p * 2 + h] = ep;                // release
    }

    // ---- Phase 3 prologue: q + idx loads issued before the flag wait so
    // their DRAM latency overlaps the spin.
    const int2   ii = ((const int2*)idx)[base >> 5];
    const float4 qv = ((const float4*)q)[base];

    // ---- Dataflow wait: warp = one token (lanes span d4) -> exactly 4 rows.
    {
        const int f0 = ii.x * 2, f1 = ii.y * 2;
        if (lane == 0) {
            while (g_flag[f0] < ep || g_flag[f0 + 1] < ep ||
                   g_flag[f1] < ep || g_flag[f1 + 1] < ep)
                __nanosleep(64);
        }
        __syncwarp();
    }

    // ---- Phase 3: one float4 per thread; P rows L2-resident (L1 is clean
    // this launch, producer stores went through L2 before the flag).
    {
        const int d4 = base & 31;
        const float4* P0 = (const float4*)g_P;     // half-0 rows
        const float4* P1 = P0 + NP * (Dd / 4);     // half-1 rows
        float4 a0 = P0[ii.x * 32 + d4];
        float4 b0 = P1[ii.x * 32 + d4];
        float4 a1 = P0[ii.y * 32 + d4];
        float4 b1 = P1[ii.y * 32 + d4];
        float4 o;
        o.x = ((a0.x + b0.x) + (a1.x + b1.x)) * qv.x;
        o.y = ((a0.y + b0.y) + (a1.y + b1.y)) * qv.y;
        o.z = ((a0.z + b0.z) + (a1.z + b1.z)) * qv.z;
        o.w = ((a0.w + b0.w) + (a1.w + b1.w)) * qv.w;
        ((float4*)out)[base] = o;
    }
}

extern "C" void kernel_launch(void* const* d_in, const int* in_sizes, int n_in,
                              void* d_out, int out_size)
{
    const int*   idx     = (const int*)  d_in[0];  // [B,S,K] int32
    const float* keys    = (const float*)d_in[1];  // [B,S,K,C] f32
    const float* values  = (const float*)d_in[2];  // [B,S,D]   f32
    const float* queries = (const float*)d_in[3];  // [B,S,D]   f32
    float*       out     = (float*)d_out;          // [B,S,D]   f32

    (void)in_sizes; (void)n_in; (void)out_size;

    k_fused<<<NBLK, NTHR>>>(idx, keys, values, queries, out);
}

// round 12
// speedup vs baseline: 2.4175x; 2.4175x over previous
#include <cuda_runtime.h>
#include <cstdint>

// Fixed problem shapes
static constexpr int NP     = 128;           // partitions
static constexpr int Cc     = 32;            // key channels
static constexpr int Dd     = 128;           // value/query dim
static constexpr int Bb     = 4;
static constexpr int Ss     = 2048;
static constexpr int Kk     = 2;
static constexpr int NPAIRS = Bb * Ss * Kk;  // 16384
static constexpr int NTOK   = Bb * Ss;       // 8192

static constexpr int NTHR   = 1024;
static constexpr int NBLK   = 2 * NP;        // 256 blocks = (partition, half)
static constexpr int HALFN  = NPAIRS / 2;    // 8192 pairs per half
static constexpr int PER    = HALFN / 4 / NTHR;    // 2 int4 per thread
static constexpr int CAP    = 512;           // per-(p,half) capacity (mean 64, sigma 8)

static constexpr int ONTHR  = 256;
static constexpr int ONBLK  = NTOK * Dd / 4 / ONTHR;  // 1024 blocks, 1 f4/thread

// Persistent scratch: per-(half,partition) partial rows. Fully rewritten by
// k_scatter every launch (gather formulation -> no zeroing, no atomics).
__device__ float g_P[2 * NP * Dd];

// ---------------------------------------------------------------------------
// k_scatter: 256 blocks x 1024 threads, 2 CTAs/SM. Block (p,h):
//   Phase 1:   scan half h of idx (2 int4/thread, strided-coalesced),
//              two-level shfl scan -> deterministic compaction (~64 matches).
//   Phase 1.5: w[m] = mean_c keys[j_m,:], 8 threads/row octet-shfl.
//   Phase 2:   float4 gather thread=(slice,d4); transpose + warp-shfl
//              reduce -> g_P[h][p] row. Done. (No barrier — kernel boundary.)
// ---------------------------------------------------------------------------
__global__ void __launch_bounds__(NTHR, 2) k_scatter(
    const int*   __restrict__ idx,
    const float* __restrict__ keys,
    const float* __restrict__ values)
{
    __shared__ int    js[CAP];
    __shared__ float  wls[CAP];
    __shared__ int    wsum[32];
    __shared__ float4 red4[32][33];          // padded transpose buffer

    const int p    = blockIdx.x >> 1;
    const int h    = blockIdx.x & 1;
    const int tid  = threadIdx.x;
    const int lane = tid & 31;
    const int wid  = tid >> 5;

    // ---- Phase 1a: strided-coalesced idx load (2 int4/thread), count
    const int4* idx4 = (const int4*)idx + h * (HALFN / 4);
    int4 my[PER];
    int cnt = 0;
    #pragma unroll
    for (int i = 0; i < PER; i++) {
        my[i] = idx4[i * NTHR + tid];
        cnt += (my[i].x == p) + (my[i].y == p) + (my[i].z == p) + (my[i].w == p);
    }

    // ---- Phase 1b: two-level exclusive scan (warp shfl + 32-entry top)
    int inc = cnt;
    #pragma unroll
    for (int o = 1; o < 32; o <<= 1) {
        int v = __shfl_up_sync(0xFFFFFFFFu, inc, o);
        if (lane >= o) inc += v;
    }
    if (lane == 31) wsum[wid] = inc;
    __syncthreads();
    if (wid == 0) {
        int v = wsum[lane];
        #pragma unroll
        for (int o = 1; o < 32; o <<= 1) {
            int u = __shfl_up_sync(0xFFFFFFFFu, v, o);
            if (lane >= o) v += u;
        }
        wsum[lane] = v;                      // inclusive prefix of warp totals
    }
    __syncthreads();
    int n   = wsum[31];
    int pos = (wid ? wsum[wid - 1] : 0) + (inc - cnt);

    // ---- Phase 1c: emit matched pair indices (fixed deterministic order)
    #pragma unroll
    for (int i = 0; i < PER; i++) {
        const int j = h * HALFN + (i * NTHR + tid) * 4;
        if (my[i].x == p && pos < CAP) js[pos++] = j + 0;
        if (my[i].y == p && pos < CAP) js[pos++] = j + 1;
        if (my[i].z == p && pos < CAP) js[pos++] = j + 2;
        if (my[i].w == p && pos < CAP) js[pos++] = j + 3;
    }
    if (n > CAP) n = CAP;
    __syncthreads();

    // ---- Phase 1.5: weights, 8 threads per 128B key row, octet shfl.
    {
        const int lane8 = tid & 7;
        const int row8  = tid >> 3;
        for (int b = 0; b < n; b += NTHR / 8) {
            const int m = b + row8;
            float s = 0.f;
            if (m < n) {
                float4 v = ((const float4*)keys)[(size_t)js[m] * (Cc / 4) + lane8];
                s = (v.x + v.y) + (v.z + v.w);
            }
            s += __shfl_xor_sync(0xFFFFFFFFu, s, 1);
            s += __shfl_xor_sync(0xFFFFFFFFu, s, 2);
            s += __shfl_xor_sync(0xFFFFFFFFu, s, 4);
            if (m < n && lane8 == 0) wls[m] = s * (1.0f / Cc);
        }
    }
    __syncthreads();

    // ---- Phase 2: float4 gather, thread=(slice,d4); ~2 matches/thread.
    {
        const int slice = tid >> 5;
        const int d4    = tid & 31;
        const float4* V4 = (const float4*)values;
        float4 acc = make_float4(0.f, 0.f, 0.f, 0.f);
        for (int m = slice; m < n; m += 32) {
            const float w = wls[m];
            float4 v = V4[(js[m] >> 1) * 32 + d4];
            acc.x += w * v.x; acc.y += w * v.y;
            acc.z += w * v.z; acc.w += w * v.w;
        }
        red4[slice][d4] = acc;
        __syncthreads();
        // warp-transpose reduce: warp `wid` owns column d4=wid, lanes=slices
        float4 v = red4[lane][wid];
        #pragma unroll
        for (int o = 16; o >= 1; o >>= 1) {
            v.x += __shfl_down_sync(0xFFFFFFFFu, v.x, o);
            v.y += __shfl_down_sync(0xFFFFFFFFu, v.y, o);
            v.z += __shfl_down_sync(0xFFFFFFFFu, v.z, o);
            v.w += __shfl_down_sync(0xFFFFFFFFu, v.w, o);
        }
        if (lane == 0)
            ((float4*)g_P)[(h * NP + p) * 32 + wid] = v;
    }
}

// ---------------------------------------------------------------------------
// k_out: fresh full grid, pure stream. 1024 blocks x 256 threads, exactly one
// float4 per thread: out = (P0[i0]+P1[i0]+P0[i1]+P1[i1]) * q.
// P rows (128KB) are L2-resident from k_scatter's stores.
// ---------------------------------------------------------------------------
__global__ void __launch_bounds__(ONTHR) k_out(
    const int*   __restrict__ idx,
    const float* __restrict__ q,
    float*       __restrict__ out)
{
    const int i   = blockIdx.x * ONTHR + threadIdx.x;  // 0 .. 262143
    const int tok = i >> 5;                            // 32 float4 per token
    const int d4  = i & 31;
    const int2 ii = __ldg((const int2*)idx + tok);
    const float4* P0 = (const float4*)g_P;             // half-0 rows
    const float4* P1 = P0 + NP * (Dd / 4);             // half-1 rows
    float4 a0 = P0[ii.x * 32 + d4];
    float4 b0 = P1[ii.x * 32 + d4];
    float4 a1 = P0[ii.y * 32 + d4];
    float4 b1 = P1[ii.y * 32 + d4];
    float4 qv = __ldg((const float4*)q + i);
    float4 o;
    o.x = ((a0.x + b0.x) + (a1.x + b1.x)) * qv.x;
    o.y = ((a0.y + b0.y) + (a1.y + b1.y)) * qv.y;
    o.z = ((a0.z + b0.z) + (a1.z + b1.z)) * qv.z;
    o.w = ((a0.w + b0.w) + (a1.w + b1.w)) * qv.w;
    ((float4*)out)[i] = o;
}

extern "C" void kernel_launch(void* const* d_in, const int* in_sizes, int n_in,
                              void* d_out, int out_size)
{
    const int*   idx     = (const int*)  d_in[0];  // [B,S,K] int32
    const float* keys    = (const float*)d_in[1];  // [B,S,K,C] f32
    const float* values  = (const float*)d_in[2];  // [B,S,D]   f32
    const float* queries = (const float*)d_in[3];  // [B,S,D]   f32
    float*       out     = (float*)d_out;          // [B,S,D]   f32

    (void)in_sizes; (void)n_in; (void)out_size;

    k_scatter<<<NBLK, NTHR>>>(idx, keys, values);
    k_out<<<ONBLK, ONTHR>>>(idx, queries, out);
}

// round 13
// speedup vs baseline: 2.4358x; 1.0076x over previous
#include <cuda_runtime.h>
#include <cstdint>

// Fixed problem shapes
static constexpr int NP     = 128;           // partitions
static constexpr int Cc     = 32;            // key channels
static constexpr int Dd     = 128;           // value/query dim
static constexpr int Bb     = 4;
static constexpr int Ss     = 2048;
static constexpr int Kk     = 2;
static constexpr int NPAIRS = Bb * Ss * Kk;  // 16384
static constexpr int NTOK   = Bb * Ss;       // 8192

static constexpr int NTHR   = 1024;
static constexpr int NBLK   = 2 * NP;        // 256 blocks = (partition, half)
static constexpr int HALFN  = NPAIRS / 2;    // 8192 pairs per half
static constexpr int PER    = HALFN / 4 / NTHR;    // 2 int4 per thread
static constexpr int CAP    = 512;           // per-(p,half) capacity (mean 64, sigma 8)

static constexpr int ONTHR  = 256;
static constexpr int ONBLK  = NTOK * Dd / 4 / ONTHR;  // 1024 blocks, 1 f4/thread

// Persistent scratch: per-(half,partition) partial rows. Fully rewritten by
// k_scatter every launch (gather formulation -> no zeroing, no atomics).
__device__ float g_P[2 * NP * Dd];
__device__ float g_sink;                     // dead-store sink for q-warm loads

// ---------------------------------------------------------------------------
// k_scatter: 256 blocks x 1024 threads, 2 CTAs/SM. Block (p,h):
//   Entry:     L2-warm q — 256K threads x 1 float4 covers the whole q tensor;
//              the load is kept alive by a never-true predicated store (a sum
//              of finite floats can't be NaN -> condition never fires, but
//              the compiler can't prove it). Overlaps the latency-bound
//              phases below; k_out then reads q from L2.
//   Phase 1:   scan half h of idx (2 int4/thread, strided-coalesced),
//              two-level shfl scan -> deterministic compaction (~64 matches).
//   Phase 1.5: w[m] = mean_c keys[j_m,:], 8 threads/row octet-shfl.
//   Phase 2:   float4 gather thread=(slice,d4); transpose + warp-shfl
//              reduce -> g_P[h][p] row. Done. (No barrier — kernel boundary.)
// ---------------------------------------------------------------------------
__global__ void __launch_bounds__(NTHR, 2) k_scatter(
    const int*   __restrict__ idx,
    const float* __restrict__ keys,
    const float* __restrict__ values,
    const float* __restrict__ q)
{
    __shared__ int    js[CAP];
    __shared__ float  wls[CAP];
    __shared__ int    wsum[32];
    __shared__ float4 red4[32][33];          // padded transpose buffer

    const int p    = blockIdx.x >> 1;
    const int h    = blockIdx.x & 1;
    const int tid  = threadIdx.x;
    const int lane = tid & 31;
    const int wid  = tid >> 5;

    // ---- Entry: q L2-warm (exactly covers q: 256 blk * 1024 thr = 262144 f4)
    {
        const int gtid = blockIdx.x * NTHR + tid;
        float4 qw = __ldg((const float4*)q + gtid);
        float s = (qw.x + qw.y) + (qw.z + qw.w);
        if (__float_as_uint(s) == 0x7F800001u)   // NaN pattern: unreachable
            g_sink = s;
    }

    // ---- Phase 1a: strided-coalesced idx load (2 int4/thread), count
    const int4* idx4 = (const int4*)idx + h * (HALFN / 4);
    int4 my[PER];
    int cnt = 0;
    #pragma unroll
    for (int i = 0; i < PER; i++) {
        my[i] = idx4[i * NTHR + tid];
        cnt += (my[i].x == p) + (my[i].y == p) + (my[i].z == p) + (my[i].w == p);
    }

    // ---- Phase 1b: two-level exclusive scan (warp shfl + 32-entry top)
    int inc = cnt;
    #pragma unroll
    for (int o = 1; o < 32; o <<= 1) {
        int v = __shfl_up_sync(0xFFFFFFFFu, inc, o);
        if (lane >= o) inc += v;
    }
    if (lane == 31) wsum[wid] = inc;
    __syncthreads();
    if (wid == 0) {
        int v = wsum[lane];
        #pragma unroll
        for (int o = 1; o < 32; o <<= 1) {
            int u = __shfl_up_sync(0xFFFFFFFFu, v, o);
            if (lane >= o) v += u;
        }
        wsum[lane] = v;                      // inclusive prefix of warp totals
    }
    __syncthreads();
    int n   = wsum[31];
    int pos = (wid ? wsum[wid - 1] : 0) + (inc - cnt);

    // ---- Phase 1c: emit matched pair indices (fixed deterministic order)
    #pragma unroll
    for (int i = 0; i < PER; i++) {
        const int j = h * HALFN + (i * NTHR + tid) * 4;
        if (my[i].x == p && pos < CAP) js[pos++] = j + 0;
        if (my[i].y == p && pos < CAP) js[pos++] = j + 1;
        if (my[i].z == p && pos < CAP) js[pos++] = j + 2;
        if (my[i].w == p && pos < CAP) js[pos++] = j + 3;
    }
    if (n > CAP) n = CAP;
    __syncthreads();

    // ---- Phase 1.5: weights, 8 threads per 128B key row, octet shfl.
    {
        const int lane8 = tid & 7;
        const int row8  = tid >> 3;
        for (int b = 0; b < n; b += NTHR / 8) {
            const int m = b + row8;
            float s = 0.f;
            if (m < n) {
                float4 v = ((const float4*)keys)[(size_t)js[m] * (Cc / 4) + lane8];
                s = (v.x + v.y) + (v.z + v.w);
            }
            s += __shfl_xor_sync(0xFFFFFFFFu, s, 1);
            s += __shfl_xor_sync(0xFFFFFFFFu, s, 2);
            s += __shfl_xor_sync(0xFFFFFFFFu, s, 4);
            if (m < n && lane8 == 0) wls[m] = s * (1.0f / Cc);
        }
    }
    __syncthreads();

    // ---- Phase 2: float4 gather, thread=(slice,d4); ~2 matches/thread.
    {
        const int slice = tid >> 5;
        const int d4    = tid & 31;
        const float4* V4 = (const float4*)values;
        float4 acc = make_float4(0.f, 0.f, 0.f, 0.f);
        for (int m = slice; m < n; m += 32) {
            const float w = wls[m];
            float4 v = V4[(js[m] >> 1) * 32 + d4];
            acc.x += w * v.x; acc.y += w * v.y;
            acc.z += w * v.z; acc.w += w * v.w;
        }
        red4[slice][d4] = acc;
        __syncthreads();
        // warp-transpose reduce: warp `wid` owns column d4=wid, lanes=slices
        float4 v = red4[lane][wid];
        #pragma unroll
        for (int o = 16; o >= 1; o >>= 1) {
            v.x += __shfl_down_sync(0xFFFFFFFFu, v.x, o);
            v.y += __shfl_down_sync(0xFFFFFFFFu, v.y, o);
            v.z += __shfl_down_sync(0xFFFFFFFFu, v.z, o);
            v.w += __shfl_down_sync(0xFFFFFFFFu, v.w, o);
        }
        if (lane == 0)
            ((float4*)g_P)[(h * NP + p) * 32 + wid] = v;
    }
}

// ---------------------------------------------------------------------------
// k_out: fresh full grid, pure stream. 1024 blocks x 256 threads, exactly one
// float4 per thread: out = (P0[i0]+P1[i0]+P0[i1]+P1[i1]) * q.
// q and idx are L2-hot from k_scatter; P rows L2-resident. DRAM = out write.
// ---------------------------------------------------------------------------
__global__ void __launch_bounds__(ONTHR) k_out(
    const int*   __restrict__ idx,
    const float* __restrict__ q,
    float*       __restrict__ out)
{
    const int i   = blockIdx.x * ONTHR + threadIdx.x;  // 0 .. 262143
    const int tok = i >> 5;                            // 32 float4 per token
    const int d4  = i & 31;
    const int2 ii = __ldg((const int2*)idx + tok);
    const float4* P0 = (const float4*)g_P;             // half-0 rows
    const float4* P1 = P0 + NP * (Dd / 4);             // half-1 rows
    float4 a0 = P0[ii.x * 32 + d4];
    float4 b0 = P1[ii.x * 32 + d4];
    float4 a1 = P0[ii.y * 32 + d4];
    float4 b1 = P1[ii.y * 32 + d4];
    float4 qv = __ldg((const float4*)q + i);
    float4 o;
    o.x = ((a0.x + b0.x) + (a1.x + b1.x)) * qv.x;
    o.y = ((a0.y + b0.y) + (a1.y + b1.y)) * qv.y;
    o.z = ((a0.z + b0.z) + (a1.z + b1.z)) * qv.z;
    o.w = ((a0.w + b0.w) + (a1.w + b1.w)) * qv.w;
    ((float4*)out)[i] = o;
}

extern "C" void kernel_launch(void* const* d_in, const int* in_sizes, int n_in,
                              void* d_out, int out_size)
{
    const int*   idx     = (const int*)  d_in[0];  // [B,S,K] int32
    const float* keys    = (const float*)d_in[1];  // [B,S,K,C] f32
    const float* values  = (const float*)d_in[2];  // [B,S,D]   f32
    const float* queries = (const float*)d_in[3];  // [B,S,D]   f32
    float*       out     = (float*)d_out;          // [B,S,D]   f32

    (void)in_sizes; (void)n_in; (void)out_size;

    k_scatter<<<NBLK, NTHR>>>(idx, keys, values, queries);
    k_out<<<ONBLK, ONTHR>>>(idx, queries, out);
}